// round 3
// baseline (speedup 1.0000x reference)
#include <cuda_runtime.h>

#define B     8
#define A     49104
#define C     20
#define M     32
#define NANN  16
#define APB   32                          // anchors per block (256 thr = 32a x 8b)
#define NBLK  ((A + APB - 1) / APB)       // 1535
#define LN2F  0.6931471805599453f

// ---- scratch (device globals; every slot written every call) ----
__device__ float g_pc[B][NBLK];
__device__ float g_pr[B][NBLK];
__device__ int   g_pn[B][NBLK];
__device__ int   g_count = 0;             // last block resets -> replay-invariant

__global__ void __launch_bounds__(256) k_fused(
    const float* __restrict__ cls_in,       // [B,A,C]
    const float* __restrict__ regressions,  // [B,A,4]
    const float* __restrict__ anchors,      // [1,A,4]
    const float* __restrict__ ema_in,       // [B,A,C]
    const float* __restrict__ ema_classes,  // [B,M]
    const float* __restrict__ ema_bboxes,   // [B,M,4]
    const int*   __restrict__ ema_counts,   // [B]
    const float* __restrict__ annotations,  // [B,N,5]
    float* __restrict__ out)
{
    __shared__ float4   sbox[B][M + 1];     // +1 pad: conflict-free across b
    __shared__ unsigned skeep[B];
    __shared__ float    s_c[8][8], s_r[8][8];
    __shared__ int      s_n[8][8];
    __shared__ bool     s_last;

    const int tid  = threadIdx.x;
    const int lane = tid & 31;
    const int wrp  = tid >> 5;
    const int b    = lane & 7;                         // batch of this thread
    const int a    = blockIdx.x * APB + wrp * 4 + (lane >> 3);
    const bool valid = (a < A);
    const int  al  = valid ? a : 0;

    // ---- setup: warp w loads batch w's boxes + keep mask (8 warps x 32) ----
    {
        const int bb = wrp, m = lane;
        sbox[bb][m] = ((const float4*)ema_bboxes)[bb * M + m];
        bool vld = m < ema_counts[bb];
        float cl = ema_classes[bb * M + m];
        bool mem = false;
        #pragma unroll
        for (int n = 0; n < NANN; n++)
            mem |= (cl == annotations[(bb * NANN + n) * 5 + 4]);
        unsigned msk = __ballot_sync(0xffffffffu, vld && mem);
        if (m == 0) skeep[bb] = msk;
    }
    __syncthreads();

    // ---- per-thread assignment for (a, b): branch-free unrolled IoU scan ----
    const float4 an = ((const float4*)anchors)[al];
    const float aw = an.z - an.x, ah = an.w - an.y;
    const float acx = an.x + 0.5f * aw, acy = an.y + 0.5f * ah;
    const float area_a = aw * ah;
    const unsigned km = skeep[b];

    float best = -1.f;
    int   besti = 0;
    #pragma unroll
    for (int m = 0; m < M; m++) {
        float4 bx = sbox[b][m];
        float iw = fminf(an.z, bx.z) - fmaxf(an.x, bx.x);
        float ih = fminf(an.w, bx.w) - fmaxf(an.y, bx.y);
        iw = fmaxf(iw, 0.f);
        ih = fmaxf(ih, 0.f);
        float inter = iw * ih;
        float ab2 = (bx.z - bx.x) * (bx.w - bx.y);
        float ua = fmaxf(area_a + ab2 - inter, 1e-8f);
        float iou = ((km >> m) & 1u) ? (inter / ua) : -1.f;
        // ascending m + strict '>' == jnp first-argmax; masked -1 never wins
        bool better = iou > best;
        besti = better ? m : besti;
        best  = better ? iou : best;
    }
    const bool has      = (km != 0u) && valid;
    const bool pos      = has && (best >= 0.5f);
    const bool assigned = has && ((best < 0.4f) || (best >= 0.5f));

    // ---- regression consistency (only at pos anchors) ----
    float racc = 0.f;
    int   np   = 0;
    if (pos) {
        np = 1;
        float4 r = ((const float4*)regressions)[(size_t)b * A + al];
        float4 g = sbox[b][besti];
        float gw = g.z - g.x, gh = g.w - g.y;
        float gcx = g.x + 0.5f * gw, gcy = g.y + 0.5f * gh;
        gw = fmaxf(gw, 1.f);
        gh = fmaxf(gh, 1.f);
        float dx = (gcx - acx) / aw / 0.1f;
        float dy = (gcy - acy) / ah / 0.1f;
        float dw = __logf(gw / aw) / 0.2f;
        float dh = __logf(gh / ah) / 0.2f;
        float d;
        d = fabsf(dx - r.x); racc += (d <= 1.f / 9.f) ? 4.5f * d * d : d - 0.5f / 9.f;
        d = fabsf(dy - r.y); racc += (d <= 1.f / 9.f) ? 4.5f * d * d : d - 0.5f / 9.f;
        d = fabsf(dw - r.z); racc += (d <= 1.f / 9.f) ? 4.5f * d * d : d - 0.5f / 9.f;
        d = fabsf(dh - r.w); racc += (d <= 1.f / 9.f) ? 4.5f * d * d : d - 0.5f / 9.f;
    }

    // ---- classification consistency: 5 float4 chunks, alpha via shuffles ----
    const float4* eb = (const float4*)ema_in + ((size_t)b * A + al) * 5;
    const float4* cb = (const float4*)cls_in + ((size_t)b * A + al) * 5;
    float cacc = 0.f;

    #pragma unroll
    for (int k = 0; k < 5; k++) {
        float4 e = eb[k];                 // unclamped, needed for alpha anyway
        float4 S = e;                     // sum over the 8 batches of this anchor
        #pragma unroll
        for (int off = 1; off <= 4; off <<= 1) {
            S.x += __shfl_xor_sync(0xffffffffu, S.x, off);
            S.y += __shfl_xor_sync(0xffffffffu, S.y, off);
            S.z += __shfl_xor_sync(0xffffffffu, S.z, off);
            S.w += __shfl_xor_sync(0xffffffffu, S.w, off);
        }
        if (assigned) {
            float4 c = cb[k];
            #pragma unroll
            for (int q = 0; q < 4; q++) {
                float ev = (q == 0) ? e.x : (q == 1) ? e.y : (q == 2) ? e.z : e.w;
                float cv = (q == 0) ? c.x : (q == 1) ? c.y : (q == 2) ? c.z : c.w;
                float Sv = (q == 0) ? S.x : (q == 1) ? S.y : (q == 2) ? S.z : S.w;
                float alpha = (0.4f + 0.9f * Sv) * LN2F;    // fold ln2 of log2
                float ec = fminf(fmaxf(ev, 1e-4f), 1.f - 1e-4f);
                float cc = fminf(fmaxf(cv, 1e-4f), 1.f - 1e-4f);
                float bce2 = -(ec * __log2f(cc) + (1.f - ec) * __log2f(1.f - cc));
                float d = ec - cc;
                cacc += alpha * (d * d) * bce2;
            }
        }
    }

    // ---- reduce within warp over same-b lanes (xor 8, 16) ----
    #pragma unroll
    for (int off = 8; off <= 16; off <<= 1) {
        cacc += __shfl_xor_sync(0xffffffffu, cacc, off);
        racc += __shfl_xor_sync(0xffffffffu, racc, off);
        np   += __shfl_xor_sync(0xffffffffu, np,   off);
    }
    if (lane < 8) { s_c[wrp][b] = cacc; s_r[wrp][b] = racc; s_n[wrp][b] = np; }
    __syncthreads();

    if (tid < 8) {
        float cs = 0.f, rs = 0.f;
        int   ns = 0;
        #pragma unroll
        for (int w = 0; w < 8; w++) { cs += s_c[w][tid]; rs += s_r[w][tid]; ns += s_n[w][tid]; }
        g_pc[tid][blockIdx.x] = cs;
        g_pr[tid][blockIdx.x] = rs;
        g_pn[tid][blockIdx.x] = ns;
    }

    // ---- last-block final reduction ----
    __threadfence();
    __syncthreads();
    if (tid == 0) s_last = (atomicAdd(&g_count, 1) == (int)gridDim.x - 1);
    __syncthreads();
    if (!s_last) return;
    __threadfence();

    if (wrp < B) {
        const int bb = wrp;
        float cs = 0.f, rs = 0.f;
        int   ns = 0;
        for (int i = lane; i < NBLK; i += 32) {
            cs += g_pc[bb][i];
            rs += g_pr[bb][i];
            ns += g_pn[bb][i];
        }
        #pragma unroll
        for (int o = 16; o; o >>= 1) {
            cs += __shfl_down_sync(0xffffffffu, cs, o);
            rs += __shfl_down_sync(0xffffffffu, rs, o);
            ns += __shfl_down_sync(0xffffffffu, ns, o);
        }
        if (lane == 0) {
            float npf = (float)ns;
            float mx  = fmaxf(npf, 1.f);
            s_c[0][bb] = cs / mx;
            s_r[0][bb] = (npf > 0.f) ? rs / (4.f * mx) : 0.f;
        }
    }
    __syncthreads();
    if (tid == 0) {
        float cs = 0.f, rs = 0.f;
        #pragma unroll
        for (int bb = 0; bb < B; bb++) { cs += s_c[0][bb]; rs += s_r[0][bb]; }
        out[0] = cs * (1.f / (float)B);
        out[1] = rs * (1.f / (float)B);
        g_count = 0;
    }
}

extern "C" void kernel_launch(void* const* d_in, const int* in_sizes, int n_in,
                              void* d_out, int out_size) {
    const float* classifications     = (const float*)d_in[0];
    const float* regressions         = (const float*)d_in[1];
    const float* anchors             = (const float*)d_in[2];
    const float* ema_classifications = (const float*)d_in[3];
    const float* ema_classes         = (const float*)d_in[4];
    const float* ema_bboxes          = (const float*)d_in[5];
    const int*   ema_counts          = (const int*)d_in[6];
    const float* annotations         = (const float*)d_in[7];

    k_fused<<<NBLK, 256>>>(classifications, regressions, anchors,
                           ema_classifications, ema_classes, ema_bboxes,
                           ema_counts, annotations, (float*)d_out);
}

// round 4
// speedup vs baseline: 1.5180x; 1.5180x over previous
#include <cuda_runtime.h>

#define B     8
#define A     49104
#define C     20
#define M     32
#define NANN  16
#define APB   32                          // anchors per block
#define NBLK  ((A + APB - 1) / APB)       // 1535
#define LN2F  0.6931471805599453f

// ---- scratch (device globals; every slot written every call) ----
__device__ float g_pc[B][NBLK];
__device__ float g_pr[B][NBLK];
__device__ int   g_pn[B][NBLK];
__device__ int   g_count = 0;             // last block resets -> replay-invariant

__global__ void __launch_bounds__(256) k_fused(
    const float* __restrict__ cls_in,       // [B,A,C]
    const float* __restrict__ regressions,  // [B,A,4]
    const float* __restrict__ anchors,      // [1,A,4]
    const float* __restrict__ ema_in,       // [B,A,C]
    const float* __restrict__ ema_classes,  // [B,M]
    const float* __restrict__ ema_bboxes,   // [B,M,4]
    const int*   __restrict__ ema_counts,   // [B]
    const float* __restrict__ annotations,  // [B,N,5]
    float* __restrict__ out)
{
    __shared__ float4        s_cbox[B][M];        // compacted kept boxes (asc. m)
    __shared__ float         s_carea[B][M];
    __shared__ int           s_cnt[B];
    __shared__ unsigned char s_assigned[B][APB];
    __shared__ float         s_rw[B];
    __shared__ int           s_nw[B];
    __shared__ float         s_c[8][8];
    __shared__ bool          s_last;

    const int tid  = threadIdx.x;
    const int lane = tid & 31;
    const int wrp  = tid >> 5;

    // ================= Phase 1: warp w owns batch w =================
    const int bw = wrp;

    // -- compact kept boxes for batch bw (order-preserving => first-argmax ok)
    {
        const int m = lane;
        float4 bb4 = ((const float4*)ema_bboxes)[bw * M + m];
        bool vld = m < ema_counts[bw];
        float cl = ema_classes[bw * M + m];
        bool mem = false;
        #pragma unroll
        for (int n = 0; n < NANN; n++)
            mem |= (cl == annotations[(bw * NANN + n) * 5 + 4]);
        unsigned msk = __ballot_sync(0xffffffffu, vld && mem);
        int p = __popc(msk & ((1u << m) - 1u));
        if ((msk >> m) & 1u) {
            s_cbox[bw][p]  = bb4;
            s_carea[bw][p] = (bb4.z - bb4.x) * (bb4.w - bb4.y);
        }
        if (m == 0) s_cnt[bw] = __popc(msk);
        __syncwarp();
    }

    // -- per-lane anchor assignment (division-free argmax over kept list)
    {
        const int a = blockIdx.x * APB + lane;
        const bool valid = (a < A);
        const float4 an = ((const float4*)anchors)[valid ? a : 0];
        const float aw = an.z - an.x, ah = an.w - an.y;
        const float acx = an.x + 0.5f * aw, acy = an.y + 0.5f * ah;
        const float area_a = aw * ah;

        const int cnt = s_cnt[bw];           // uniform within warp
        float bI = -1.f, bU = 1.f;
        int   bi = 0;
        for (int m = 0; m < cnt; m++) {
            float4 bx = s_cbox[bw][m];       // LDS broadcast
            float iw = fminf(an.z, bx.z) - fmaxf(an.x, bx.x);
            float ih = fminf(an.w, bx.w) - fmaxf(an.y, bx.y);
            iw = fmaxf(iw, 0.f);
            ih = fmaxf(ih, 0.f);
            float inter = iw * ih;
            float u = fmaxf(area_a + s_carea[bw][m] - inter, 1e-8f);
            // iou_m > best  <=>  inter*bU > bI*u   (u, bU > 0)
            bool better = inter * bU > bI * u;
            bi = better ? m : bi;
            bI = better ? inter : bI;
            bU = better ? u : bU;
        }
        const bool has = (cnt > 0) && valid;
        const bool pos = has && (bI >= 0.5f * bU);
        const bool assigned = has && ((bI < 0.4f * bU) || (bI >= 0.5f * bU));
        s_assigned[bw][lane] = assigned ? (unsigned char)1 : (unsigned char)0;

        float racc = 0.f;
        if (pos) {
            float4 r = ((const float4*)regressions)[(size_t)bw * A + a];
            float4 g = s_cbox[bw][bi];
            float gw = g.z - g.x, gh = g.w - g.y;
            float gcx = g.x + 0.5f * gw, gcy = g.y + 0.5f * gh;
            gw = fmaxf(gw, 1.f);
            gh = fmaxf(gh, 1.f);
            float dx = (gcx - acx) / aw / 0.1f;
            float dy = (gcy - acy) / ah / 0.1f;
            float dw = __logf(gw / aw) / 0.2f;
            float dh = __logf(gh / ah) / 0.2f;
            float d;
            d = fabsf(dx - r.x); racc += (d <= 1.f / 9.f) ? 4.5f * d * d : d - 0.5f / 9.f;
            d = fabsf(dy - r.y); racc += (d <= 1.f / 9.f) ? 4.5f * d * d : d - 0.5f / 9.f;
            d = fabsf(dw - r.z); racc += (d <= 1.f / 9.f) ? 4.5f * d * d : d - 0.5f / 9.f;
            d = fabsf(dh - r.w); racc += (d <= 1.f / 9.f) ? 4.5f * d * d : d - 0.5f / 9.f;
        }
        unsigned pb = __ballot_sync(0xffffffffu, pos);
        #pragma unroll
        for (int o = 16; o; o >>= 1) racc += __shfl_down_sync(0xffffffffu, racc, o);
        if (lane == 0) { s_rw[bw] = racc; s_nw[bw] = __popc(pb); }
    }
    __syncthreads();

    // ============ Phase 2: cls consistency, thread = (anchor, batch) ============
    const int b    = lane & 7;
    const int aloc = wrp * 4 + (lane >> 3);
    const int a2   = blockIdx.x * APB + aloc;
    const bool v2  = (a2 < A);
    const int al2  = v2 ? a2 : 0;
    const bool assigned2 = v2 && s_assigned[b][aloc];

    const float4* eb = (const float4*)ema_in + ((size_t)b * A + al2) * 5;
    const float4* cb = (const float4*)cls_in + ((size_t)b * A + al2) * 5;
    float cacc = 0.f;

    #pragma unroll
    for (int k = 0; k < 5; k++) {
        float4 e = eb[k];                 // unclamped: needed for alpha (bug-faithful)
        float4 S = e;
        #pragma unroll
        for (int off = 1; off <= 4; off <<= 1) {
            S.x += __shfl_xor_sync(0xffffffffu, S.x, off);
            S.y += __shfl_xor_sync(0xffffffffu, S.y, off);
            S.z += __shfl_xor_sync(0xffffffffu, S.z, off);
            S.w += __shfl_xor_sync(0xffffffffu, S.w, off);
        }
        if (assigned2) {
            float4 c = cb[k];
            #pragma unroll
            for (int q = 0; q < 4; q++) {
                float ev = (q == 0) ? e.x : (q == 1) ? e.y : (q == 2) ? e.z : e.w;
                float cv = (q == 0) ? c.x : (q == 1) ? c.y : (q == 2) ? c.z : c.w;
                float Sv = (q == 0) ? S.x : (q == 1) ? S.y : (q == 2) ? S.z : S.w;
                float alpha = (0.4f + 0.9f * Sv) * LN2F;   // fold ln2 of log2
                float ec = fminf(fmaxf(ev, 1e-4f), 1.f - 1e-4f);
                float cc = fminf(fmaxf(cv, 1e-4f), 1.f - 1e-4f);
                float bce2 = -(ec * __log2f(cc) + (1.f - ec) * __log2f(1.f - cc));
                float d = ec - cc;
                cacc += alpha * (d * d) * bce2;
            }
        }
    }

    // reduce cacc over same-b lanes (xor 8,16), then across warps
    #pragma unroll
    for (int off = 8; off <= 16; off <<= 1)
        cacc += __shfl_xor_sync(0xffffffffu, cacc, off);
    if (lane < 8) s_c[wrp][b] = cacc;
    __syncthreads();

    if (tid < 8) {
        float cs = 0.f;
        #pragma unroll
        for (int w = 0; w < 8; w++) cs += s_c[w][tid];
        g_pc[tid][blockIdx.x] = cs;
        g_pr[tid][blockIdx.x] = s_rw[tid];
        g_pn[tid][blockIdx.x] = s_nw[tid];
    }

    // ================= last-block final reduction =================
    __threadfence();
    __syncthreads();
    if (tid == 0) s_last = (atomicAdd(&g_count, 1) == (int)gridDim.x - 1);
    __syncthreads();
    if (!s_last) return;
    __threadfence();

    if (wrp < B) {
        const int bb = wrp;
        float cs = 0.f, rs = 0.f;
        int   ns = 0;
        for (int i = lane; i < NBLK; i += 32) {
            cs += g_pc[bb][i];
            rs += g_pr[bb][i];
            ns += g_pn[bb][i];
        }
        #pragma unroll
        for (int o = 16; o; o >>= 1) {
            cs += __shfl_down_sync(0xffffffffu, cs, o);
            rs += __shfl_down_sync(0xffffffffu, rs, o);
            ns += __shfl_down_sync(0xffffffffu, ns, o);
        }
        if (lane == 0) {
            float npf = (float)ns;
            float mx  = fmaxf(npf, 1.f);
            s_c[0][bb] = cs / mx;
            s_c[1][bb] = (npf > 0.f) ? rs / (4.f * mx) : 0.f;
        }
    }
    __syncthreads();
    if (tid == 0) {
        float cs = 0.f, rs = 0.f;
        #pragma unroll
        for (int bb = 0; bb < B; bb++) { cs += s_c[0][bb]; rs += s_c[1][bb]; }
        out[0] = cs * (1.f / (float)B);
        out[1] = rs * (1.f / (float)B);
        g_count = 0;
    }
}

extern "C" void kernel_launch(void* const* d_in, const int* in_sizes, int n_in,
                              void* d_out, int out_size) {
    const float* classifications     = (const float*)d_in[0];
    const float* regressions         = (const float*)d_in[1];
    const float* anchors             = (const float*)d_in[2];
    const float* ema_classifications = (const float*)d_in[3];
    const float* ema_classes         = (const float*)d_in[4];
    const float* ema_bboxes          = (const float*)d_in[5];
    const int*   ema_counts          = (const int*)d_in[6];
    const float* annotations         = (const float*)d_in[7];

    k_fused<<<NBLK, 256>>>(classifications, regressions, anchors,
                           ema_classifications, ema_classes, ema_bboxes,
                           ema_counts, annotations, (float*)d_out);
}

// round 5
// speedup vs baseline: 1.5290x; 1.0072x over previous
#include <cuda_runtime.h>

#define B       8
#define A       49104
#define C       20
#define M       32
#define NANN    16
#define APB     64                        // anchors per block
#define THREADS 512
#define NBLK    ((A + APB - 1) / APB)     // 768
#define LN2F    0.6931471805599453f

// ---- scratch (device globals; every slot written every call) ----
__device__ float g_pc[B][NBLK];
__device__ float g_pr[B][NBLK];
__device__ int   g_pn[B][NBLK];
__device__ int   g_count = 0;             // last block resets -> replay-invariant

__global__ void __launch_bounds__(THREADS) k_fused(
    const float* __restrict__ cls_in,       // [B,A,C]
    const float* __restrict__ regressions,  // [B,A,4]
    const float* __restrict__ anchors,      // [1,A,4]
    const float* __restrict__ ema_in,       // [B,A,C]
    const float* __restrict__ ema_classes,  // [B,M]
    const float* __restrict__ ema_bboxes,   // [B,M,4]
    const int*   __restrict__ ema_counts,   // [B]
    const float* __restrict__ annotations,  // [B,N,5]
    float* __restrict__ out)
{
    __shared__ float4        s_cbox[B][M];        // compacted kept boxes (asc. m)
    __shared__ float         s_carea[B][M];
    __shared__ int           s_cnt[B];
    __shared__ unsigned char s_assigned[B][APB];  // row = 64B -> u32 flag reads
    __shared__ float         s_rw[16];
    __shared__ int           s_nw[16];
    __shared__ float         s_c[16][8];
    __shared__ bool          s_last;

    const int tid  = threadIdx.x;
    const int lane = tid & 31;
    const int wrp  = tid >> 5;            // 0..15
    const int b1   = wrp & 7;             // phase-1 batch
    const int h    = wrp >> 3;            // phase-1 anchor half

    // ---- compaction (warps 0..7, order-preserving => first-argmax ok) ----
    if (h == 0) {
        const int m = lane;
        float4 bb4 = ((const float4*)ema_bboxes)[b1 * M + m];
        bool vld = m < ema_counts[b1];
        float cl = ema_classes[b1 * M + m];
        bool mem = false;
        #pragma unroll
        for (int n = 0; n < NANN; n++)
            mem |= (cl == annotations[(b1 * NANN + n) * 5 + 4]);
        unsigned msk = __ballot_sync(0xffffffffu, vld && mem);
        int p = __popc(msk & ((1u << m) - 1u));
        if ((msk >> m) & 1u) {
            s_cbox[b1][p]  = bb4;
            s_carea[b1][p] = (bb4.z - bb4.x) * (bb4.w - bb4.y);
        }
        if (m == 0) s_cnt[b1] = __popc(msk);
    }
    __syncthreads();

    // ---- IoU assignment: warp w -> (batch w&7, anchors (w>>3)*32+lane) ----
    {
        const int aloc = h * 32 + lane;
        const int a = blockIdx.x * APB + aloc;
        const bool valid = (a < A);
        const float4 an = ((const float4*)anchors)[valid ? a : 0];
        const float aw = an.z - an.x, ah = an.w - an.y;
        const float acx = an.x + 0.5f * aw, acy = an.y + 0.5f * ah;
        const float area_a = aw * ah;

        const int cnt = s_cnt[b1];          // uniform within warp
        float bI = -1.f, bU = 1.f;
        int   bi = 0;
        for (int m = 0; m < cnt; m++) {
            float4 bx = s_cbox[b1][m];      // LDS broadcast
            float iw = fminf(an.z, bx.z) - fmaxf(an.x, bx.x);
            float ih = fminf(an.w, bx.w) - fmaxf(an.y, bx.y);
            iw = fmaxf(iw, 0.f);
            ih = fmaxf(ih, 0.f);
            float inter = iw * ih;
            float u = fmaxf(area_a + s_carea[b1][m] - inter, 1e-8f);
            bool better = inter * bU > bI * u;   // iou > best (u,bU > 0)
            bi = better ? m : bi;
            bI = better ? inter : bI;
            bU = better ? u : bU;
        }
        const bool has = (cnt > 0) && valid;
        const bool pos = has && (bI >= 0.5f * bU);
        const bool assigned = has && ((bI < 0.4f * bU) || (bI >= 0.5f * bU));
        s_assigned[b1][aloc] = assigned ? (unsigned char)1 : (unsigned char)0;

        float racc = 0.f;
        if (pos) {
            float4 r = ((const float4*)regressions)[(size_t)b1 * A + a];
            float4 g = s_cbox[b1][bi];
            float gw = g.z - g.x, gh = g.w - g.y;
            float gcx = g.x + 0.5f * gw, gcy = g.y + 0.5f * gh;
            gw = fmaxf(gw, 1.f);
            gh = fmaxf(gh, 1.f);
            float dx = (gcx - acx) / aw / 0.1f;
            float dy = (gcy - acy) / ah / 0.1f;
            float dw = __logf(gw / aw) / 0.2f;
            float dh = __logf(gh / ah) / 0.2f;
            float d;
            d = fabsf(dx - r.x); racc += (d <= 1.f / 9.f) ? 4.5f * d * d : d - 0.5f / 9.f;
            d = fabsf(dy - r.y); racc += (d <= 1.f / 9.f) ? 4.5f * d * d : d - 0.5f / 9.f;
            d = fabsf(dw - r.z); racc += (d <= 1.f / 9.f) ? 4.5f * d * d : d - 0.5f / 9.f;
            d = fabsf(dh - r.w); racc += (d <= 1.f / 9.f) ? 4.5f * d * d : d - 0.5f / 9.f;
        }
        unsigned pb = __ballot_sync(0xffffffffu, pos);
        #pragma unroll
        for (int o = 16; o; o >>= 1) racc += __shfl_down_sync(0xffffffffu, racc, o);
        if (lane == 0) { s_rw[wrp] = racc; s_nw[wrp] = __popc(pb); }
    }
    __syncthreads();

    // ---- phase 2: cls consistency, k-interleaved coalesced mapping ----
    // warp wrp covers anchors [wrp*4, wrp*4+4); float4 index = wrp*20 + 4k + g
    const int b = lane & 7;
    const int g = lane >> 3;

    // all 4 anchor flags for this (b, warp) in one aligned u32 LDS
    const unsigned flagsWord =
        *(const unsigned*)&s_assigned[b][wrp * 4];

    const size_t rowbase = (size_t)b * (A * 5) +
                           (size_t)blockIdx.x * (APB * 5) + wrp * 20;
    const float4* e4 = (const float4*)ema_in;
    const float4* c4 = (const float4*)cls_in;

    float cacc = 0.f;
    #pragma unroll
    for (int k = 0; k < 5; k++) {
        const int fo   = 4 * k + g;                  // 0..19
        const int ai   = fo / 5;                     // local anchor 0..3
        const int a2   = blockIdx.x * APB + wrp * 4 + ai;
        const bool v2  = (a2 < A);
        const size_t idx = v2 ? (rowbase + fo) : 0;

        float4 e = e4[idx];            // unclamped: needed for alpha (bug-faithful)
        float4 S = e;
        #pragma unroll
        for (int off = 1; off <= 4; off <<= 1) {     // sum over 8 batches
            S.x += __shfl_xor_sync(0xffffffffu, S.x, off);
            S.y += __shfl_xor_sync(0xffffffffu, S.y, off);
            S.z += __shfl_xor_sync(0xffffffffu, S.z, off);
            S.w += __shfl_xor_sync(0xffffffffu, S.w, off);
        }
        float4 c = c4[idx];
        float flag = (float)((flagsWord >> (ai * 8)) & 1u);  // 0 if invalid/unassigned

        float t = 0.f;
        #pragma unroll
        for (int q = 0; q < 4; q++) {
            float ev = (q == 0) ? e.x : (q == 1) ? e.y : (q == 2) ? e.z : e.w;
            float cv = (q == 0) ? c.x : (q == 1) ? c.y : (q == 2) ? c.z : c.w;
            float Sv = (q == 0) ? S.x : (q == 1) ? S.y : (q == 2) ? S.z : S.w;
            float alpha = (0.4f + 0.9f * Sv) * LN2F;         // fold ln2 of log2
            float ec = fminf(fmaxf(ev, 1e-4f), 1.f - 1e-4f);
            float cc = fminf(fmaxf(cv, 1e-4f), 1.f - 1e-4f);
            float bce2 = -(ec * __log2f(cc) + (1.f - ec) * __log2f(1.f - cc));
            float d = ec - cc;
            t += alpha * (d * d) * bce2;
        }
        cacc += flag * t;
    }

    // reduce cacc over same-b lanes (xor 8,16), then across 16 warps
    #pragma unroll
    for (int off = 8; off <= 16; off <<= 1)
        cacc += __shfl_xor_sync(0xffffffffu, cacc, off);
    if (lane < 8) s_c[wrp][b] = cacc;
    __syncthreads();

    if (tid < 8) {
        float cs = 0.f;
        #pragma unroll
        for (int w = 0; w < 16; w++) cs += s_c[w][tid];
        g_pc[tid][blockIdx.x] = cs;
        g_pr[tid][blockIdx.x] = s_rw[tid] + s_rw[tid + 8];
        g_pn[tid][blockIdx.x] = s_nw[tid] + s_nw[tid + 8];
    }

    // ---- last-block final reduction ----
    __threadfence();
    __syncthreads();
    if (tid == 0) s_last = (atomicAdd(&g_count, 1) == (int)gridDim.x - 1);
    __syncthreads();
    if (!s_last) return;
    __threadfence();

    if (wrp < B) {
        const int bb = wrp;
        float cs = 0.f, rs = 0.f;
        int   ns = 0;
        #pragma unroll 4
        for (int i = lane; i < NBLK; i += 32) {
            cs += g_pc[bb][i];
            rs += g_pr[bb][i];
            ns += g_pn[bb][i];
        }
        #pragma unroll
        for (int o = 16; o; o >>= 1) {
            cs += __shfl_down_sync(0xffffffffu, cs, o);
            rs += __shfl_down_sync(0xffffffffu, rs, o);
            ns += __shfl_down_sync(0xffffffffu, ns, o);
        }
        if (lane == 0) {
            float npf = (float)ns;
            float mx  = fmaxf(npf, 1.f);
            s_c[0][bb] = cs / mx;
            s_c[1][bb] = (npf > 0.f) ? rs / (4.f * mx) : 0.f;
        }
    }
    __syncthreads();
    if (tid == 0) {
        float cs = 0.f, rs = 0.f;
        #pragma unroll
        for (int bb = 0; bb < B; bb++) { cs += s_c[0][bb]; rs += s_c[1][bb]; }
        out[0] = cs * (1.f / (float)B);
        out[1] = rs * (1.f / (float)B);
        g_count = 0;
    }
}

extern "C" void kernel_launch(void* const* d_in, const int* in_sizes, int n_in,
                              void* d_out, int out_size) {
    const float* classifications     = (const float*)d_in[0];
    const float* regressions         = (const float*)d_in[1];
    const float* anchors             = (const float*)d_in[2];
    const float* ema_classifications = (const float*)d_in[3];
    const float* ema_classes         = (const float*)d_in[4];
    const float* ema_bboxes          = (const float*)d_in[5];
    const int*   ema_counts          = (const int*)d_in[6];
    const float* annotations         = (const float*)d_in[7];

    k_fused<<<NBLK, THREADS>>>(classifications, regressions, anchors,
                               ema_classifications, ema_classes, ema_bboxes,
                               ema_counts, annotations, (float*)d_out);
}

// round 6
// speedup vs baseline: 2.1531x; 1.4082x over previous
#include <cuda_runtime.h>

#define B       8
#define A       49104
#define C       20
#define M       32
#define NANN    16
#define APB     64                        // anchors per block
#define THREADS 320                       // = APB*5 float4 columns
#define NBLK    ((A + APB - 1) / APB)     // 768
#define A5      (A * 5)                   // float4 cols per batch plane
#define LN2F    0.6931471805599453f

// ---- scratch (device globals; every slot written every call) ----
__device__ float g_pc[B][NBLK];
__device__ float g_pr[B][NBLK];
__device__ int   g_pn[B][NBLK];
__device__ int   g_count = 0;             // last block resets -> replay-invariant

__global__ void __launch_bounds__(THREADS) k_fused(
    const float* __restrict__ cls_in,       // [B,A,C]
    const float* __restrict__ regressions,  // [B,A,4]
    const float* __restrict__ anchors,      // [1,A,4]
    const float* __restrict__ ema_in,       // [B,A,C]
    const float* __restrict__ ema_classes,  // [B,M]
    const float* __restrict__ ema_bboxes,   // [B,M,4]
    const int*   __restrict__ ema_counts,   // [B]
    const float* __restrict__ annotations,  // [B,N,5]
    float* __restrict__ out)
{
    __shared__ float4   s_cbox[B][M];       // compacted kept boxes (asc. m)
    __shared__ float    s_carea[B][M];
    __shared__ unsigned s_abits[B][2];      // assigned bitmask, bit = local anchor
    __shared__ float    s_rw[B];
    __shared__ int      s_nw[B];
    __shared__ float    s_c[10][8];
    __shared__ bool     s_last;

    const int tid  = threadIdx.x;
    const int lane = tid & 31;
    const int wrp  = tid >> 5;              // 0..9

    // ================= Phase 1: warps 0..7, warp = batch =================
    if (wrp < 8) {
        const int b = wrp;

        // -- compact kept boxes (order-preserving => first-argmax semantics)
        float4 bb4 = ((const float4*)ema_bboxes)[b * M + lane];
        bool vld = lane < ema_counts[b];
        float cl = ema_classes[b * M + lane];
        bool mem = false;
        #pragma unroll
        for (int n = 0; n < NANN; n++)
            mem |= (cl == annotations[(b * NANN + n) * 5 + 4]);
        unsigned msk = __ballot_sync(0xffffffffu, vld && mem);
        int p = __popc(msk & ((1u << lane) - 1u));
        if ((msk >> lane) & 1u) {
            s_cbox[b][p]  = bb4;
            s_carea[b][p] = (bb4.z - bb4.x) * (bb4.w - bb4.y);
        }
        const int cnt = __popc(msk);        // uniform in warp
        __syncwarp();

        // -- IoU assignment over both anchor halves
        float racc = 0.f;
        int   np   = 0;
        #pragma unroll
        for (int h = 0; h < 2; h++) {
            const int aloc = h * 32 + lane;
            const int a = blockIdx.x * APB + aloc;
            const bool valid = (a < A);
            const float4 an = ((const float4*)anchors)[valid ? a : 0];
            const float aw = an.z - an.x, ah = an.w - an.y;
            const float acx = an.x + 0.5f * aw, acy = an.y + 0.5f * ah;
            const float area_a = aw * ah;

            float bI = -1.f, bU = 1.f;
            int   bi = 0;
            for (int m = 0; m < cnt; m++) {
                float4 bx = s_cbox[b][m];   // LDS broadcast
                float iw = fminf(an.z, bx.z) - fmaxf(an.x, bx.x);
                float ih = fminf(an.w, bx.w) - fmaxf(an.y, bx.y);
                iw = fmaxf(iw, 0.f);
                ih = fmaxf(ih, 0.f);
                float inter = iw * ih;
                float u = fmaxf(area_a + s_carea[b][m] - inter, 1e-8f);
                bool better = inter * bU > bI * u;   // iou > best (u,bU > 0)
                bi = better ? m : bi;
                bI = better ? inter : bI;
                bU = better ? u : bU;
            }
            const bool has = (cnt > 0) && valid;
            const bool pos = has && (bI >= 0.5f * bU);
            const bool assigned = has && ((bI < 0.4f * bU) || (bI >= 0.5f * bU));

            unsigned ab = __ballot_sync(0xffffffffu, assigned);
            unsigned pb = __ballot_sync(0xffffffffu, pos);
            if (lane == 0) s_abits[b][h] = ab;
            np += __popc(pb);

            if (pos) {
                float4 r = ((const float4*)regressions)[(size_t)b * A + a];
                float4 g = s_cbox[b][bi];
                float gw = g.z - g.x, gh = g.w - g.y;
                float gcx = g.x + 0.5f * gw, gcy = g.y + 0.5f * gh;
                gw = fmaxf(gw, 1.f);
                gh = fmaxf(gh, 1.f);
                float dx = (gcx - acx) / aw / 0.1f;
                float dy = (gcy - acy) / ah / 0.1f;
                float dw = __logf(gw / aw) / 0.2f;
                float dh = __logf(gh / ah) / 0.2f;
                float d;
                d = fabsf(dx - r.x); racc += (d <= 1.f/9.f) ? 4.5f*d*d : d - 0.5f/9.f;
                d = fabsf(dy - r.y); racc += (d <= 1.f/9.f) ? 4.5f*d*d : d - 0.5f/9.f;
                d = fabsf(dw - r.z); racc += (d <= 1.f/9.f) ? 4.5f*d*d : d - 0.5f/9.f;
                d = fabsf(dh - r.w); racc += (d <= 1.f/9.f) ? 4.5f*d*d : d - 0.5f/9.f;
            }
        }
        #pragma unroll
        for (int o = 16; o; o >>= 1) racc += __shfl_down_sync(0xffffffffu, racc, o);
        if (lane == 0) { s_rw[b] = racc; s_nw[b] = np; }
    }
    __syncthreads();

    // ========== Phase 2: thread = one float4 column (one anchor, chunk k) ==========
    const int  fcol = blockIdx.x * THREADS + tid;  // global float4 col in a plane
    const bool v2   = (fcol < A5);
    const int  idx0 = v2 ? fcol : 0;
    const int  aloc = tid / 5;                     // local anchor 0..63
    const int  h2   = aloc >> 5;
    const int  bit2 = aloc & 31;

    const float4* e4 = (const float4*)ema_in;
    const float4* c4 = (const float4*)cls_in;

    // pass 1: alpha sum over batches (bug-faithful: unclamped ema)
    float4 S = make_float4(0.f, 0.f, 0.f, 0.f);
    #pragma unroll
    for (int b = 0; b < 8; b++) {
        float4 e = e4[b * A5 + idx0];
        S.x += e.x; S.y += e.y; S.z += e.z; S.w += e.w;
    }
    const float ax = (0.4f + 0.9f * S.x) * LN2F;
    const float ay = (0.4f + 0.9f * S.y) * LN2F;
    const float az = (0.4f + 0.9f * S.z) * LN2F;
    const float aw2 = (0.4f + 0.9f * S.w) * LN2F;

    // pass 2: per-batch focal BCE (e re-read: L1/L2 resident)
    float cacc[8];
    #pragma unroll
    for (int b = 0; b < 8; b++) {
        float4 e = e4[b * A5 + idx0];
        float4 c = c4[b * A5 + idx0];
        float flag = (float)((s_abits[b][h2] >> bit2) & 1u);

        float t = 0.f;
        {
            float ec = fminf(fmaxf(e.x, 1e-4f), 1.f - 1e-4f);
            float cc = fminf(fmaxf(c.x, 1e-4f), 1.f - 1e-4f);
            float bce2 = -(ec * __log2f(cc) + (1.f - ec) * __log2f(1.f - cc));
            float d = ec - cc;
            t += ax * (d * d) * bce2;
        }
        {
            float ec = fminf(fmaxf(e.y, 1e-4f), 1.f - 1e-4f);
            float cc = fminf(fmaxf(c.y, 1e-4f), 1.f - 1e-4f);
            float bce2 = -(ec * __log2f(cc) + (1.f - ec) * __log2f(1.f - cc));
            float d = ec - cc;
            t += ay * (d * d) * bce2;
        }
        {
            float ec = fminf(fmaxf(e.z, 1e-4f), 1.f - 1e-4f);
            float cc = fminf(fmaxf(c.z, 1e-4f), 1.f - 1e-4f);
            float bce2 = -(ec * __log2f(cc) + (1.f - ec) * __log2f(1.f - cc));
            float d = ec - cc;
            t += az * (d * d) * bce2;
        }
        {
            float ec = fminf(fmaxf(e.w, 1e-4f), 1.f - 1e-4f);
            float cc = fminf(fmaxf(c.w, 1e-4f), 1.f - 1e-4f);
            float bce2 = -(ec * __log2f(cc) + (1.f - ec) * __log2f(1.f - cc));
            float d = ec - cc;
            t += aw2 * (d * d) * bce2;
        }
        cacc[b] = flag * t;
    }

    // per-warp reduce each batch accumulator, then cross-warp via smem
    #pragma unroll
    for (int b = 0; b < 8; b++) {
        float v = cacc[b];
        #pragma unroll
        for (int o = 16; o; o >>= 1) v += __shfl_xor_sync(0xffffffffu, v, o);
        cacc[b] = v;
    }
    if (lane == 0) {
        #pragma unroll
        for (int b = 0; b < 8; b++) s_c[wrp][b] = cacc[b];
    }
    __syncthreads();

    if (tid < 8) {
        float cs = 0.f;
        #pragma unroll
        for (int w = 0; w < 10; w++) cs += s_c[w][tid];
        g_pc[tid][blockIdx.x] = cs;
        g_pr[tid][blockIdx.x] = s_rw[tid];
        g_pn[tid][blockIdx.x] = s_nw[tid];
    }

    // ================= last-block final reduction =================
    __threadfence();
    __syncthreads();
    if (tid == 0) s_last = (atomicAdd(&g_count, 1) == (int)gridDim.x - 1);
    __syncthreads();
    if (!s_last) return;
    __threadfence();

    if (wrp < 8) {
        const int bb = wrp;
        float cs = 0.f, rs = 0.f;
        int   ns = 0;
        #pragma unroll 4
        for (int i = lane; i < NBLK; i += 32) {
            cs += g_pc[bb][i];
            rs += g_pr[bb][i];
            ns += g_pn[bb][i];
        }
        #pragma unroll
        for (int o = 16; o; o >>= 1) {
            cs += __shfl_down_sync(0xffffffffu, cs, o);
            rs += __shfl_down_sync(0xffffffffu, rs, o);
            ns += __shfl_down_sync(0xffffffffu, ns, o);
        }
        if (lane == 0) {
            float npf = (float)ns;
            float mx  = fmaxf(npf, 1.f);
            s_c[0][bb] = cs / mx;
            s_c[1][bb] = (npf > 0.f) ? rs / (4.f * mx) : 0.f;
        }
    }
    __syncthreads();
    if (tid == 0) {
        float cs = 0.f, rs = 0.f;
        #pragma unroll
        for (int bb = 0; bb < 8; bb++) { cs += s_c[0][bb]; rs += s_c[1][bb]; }
        out[0] = cs * 0.125f;
        out[1] = rs * 0.125f;
        g_count = 0;
    }
}

extern "C" void kernel_launch(void* const* d_in, const int* in_sizes, int n_in,
                              void* d_out, int out_size) {
    const float* classifications     = (const float*)d_in[0];
    const float* regressions         = (const float*)d_in[1];
    const float* anchors             = (const float*)d_in[2];
    const float* ema_classifications = (const float*)d_in[3];
    const float* ema_classes         = (const float*)d_in[4];
    const float* ema_bboxes          = (const float*)d_in[5];
    const int*   ema_counts          = (const int*)d_in[6];
    const float* annotations         = (const float*)d_in[7];

    k_fused<<<NBLK, THREADS>>>(classifications, regressions, anchors,
                               ema_classifications, ema_classes, ema_bboxes,
                               ema_counts, annotations, (float*)d_out);
}